// round 5
// baseline (speedup 1.0000x reference)
#include <cuda_runtime.h>
#include <cuda_bf16.h>
#include <math.h>
#include <stdint.h>

#define NNODES 50000
#define KNEI   32
#define DIM    128
#define DOUT   128
#define KTOT   512
#define BM     128
#define BK     32

#define SSTR   36                     // A-stage row stride (u32)
#define BSTR   136                    // B-stage row stride (u32), [k][n] layout
#define MSTR   132                    // mean-buffer row stride (u32)
#define A_U32  (BM * SSTR)            // 4608
#define B_U32  (BK * BSTR)            // 4352
#define STAGE_U32 (A_U32 + B_U32)     // 8960
#define M1_OFF (2 * STAGE_U32)        // 17920
#define M2_OFF (M1_OFF + BM * MSTR)   // 34816
#define SMEM_U32 (M2_OFF + BM * MSTR) // 51712 u32 = 206848 B

__device__ __forceinline__ uint32_t f2tf32(float f) {
    uint32_t u;
    asm("cvt.rna.tf32.f32 %0, %1;" : "=r"(u) : "f"(f));
    return u;
}
__device__ __forceinline__ uint32_t smem_u32p(const void* p) {
    uint32_t a;
    asm("{ .reg .u64 t; cvta.to.shared.u64 t, %1; cvt.u32.u64 %0, t; }" : "=r"(a) : "l"(p));
    return a;
}
__device__ __forceinline__ void cp_async16(uint32_t dst, const void* src) {
    asm volatile("cp.async.cg.shared.global [%0], [%1], 16;"
                 :: "r"(dst), "l"(src) : "memory");
}
#define CP_COMMIT() asm volatile("cp.async.commit_group;" ::: "memory")
#define CP_WAIT0()  asm volatile("cp.async.wait_group 0;"  ::: "memory")

__device__ __forceinline__ void mma_tf32(float c[4], const uint32_t a[4],
                                         const uint32_t b[2]) {
    asm volatile(
        "mma.sync.aligned.m16n8k8.row.col.f32.tf32.tf32.f32 "
        "{%0,%1,%2,%3}, {%4,%5,%6,%7}, {%8,%9}, {%0,%1,%2,%3};"
        : "+f"(c[0]), "+f"(c[1]), "+f"(c[2]), "+f"(c[3])
        : "r"(a[0]), "r"(a[1]), "r"(a[2]), "r"(a[3]), "r"(b[0]), "r"(b[1]));
}

// ---------------------------------------------------------------------------
// Fused kernel: per 128-row CTA:
//   chunks 0..7  : MMA over fea1/fea2 (raw fp32 via cp.async, RN-cvt in regs)
//                  + concurrently gather/mean 2 nodes per warp per chunk
//                  into SMEM mean buffers (RN tf32).
//   chunks 8..15 : MMA with A-fragments read directly from mean buffers.
//   epilogue     : tanh + store.
// ---------------------------------------------------------------------------
__global__ __launch_bounds__(256, 1)
void fused_kernel(const float* __restrict__ fea1,
                  const float* __restrict__ fea2,
                  const int*   __restrict__ idx1,
                  const int*   __restrict__ idx2,
                  const float* __restrict__ W,
                  float* __restrict__ out) {
    extern __shared__ uint32_t smem[];

    const int tid  = threadIdx.x;
    const int wid  = tid >> 5;
    const int lane = tid & 31;
    const int gid  = lane >> 2;            // 0..7
    const int tig  = lane & 3;             // 0..3
    const int warp_m = (wid >> 2) * 64;    // 0 / 64
    const int warp_n = (wid & 3) * 32;     // 0,32,64,96
    const int block_row = blockIdx.x * BM;
    const uint32_t sbase = smem_u32p(smem);

    // ---- cp.async loaders ----
    auto load_A = [&](int kc, int stage) {         // kc in 0..7 only
        const float* F = (kc < 4) ? fea1 : fea2;
        const int colb = (kc & 3) * BK;
        const uint32_t aB = sbase + stage * (STAGE_U32 * 4);
        #pragma unroll
        for (int i = 0; i < 4; i++) {
            int u  = tid + i * 256;
            int r  = u >> 3;               // 0..127
            int c4 = u & 7;                // 0..7
            int gr = block_row + r;
            if (gr >= NNODES) gr = NNODES - 1;
            cp_async16(aB + r * (SSTR * 4) + c4 * 16,
                       F + (size_t)gr * DIM + colb + c4 * 4);
        }
    };
    auto load_B = [&](int kc, int stage) {
        const uint32_t bB = sbase + stage * (STAGE_U32 * 4) + A_U32 * 4;
        #pragma unroll
        for (int i = 0; i < 4; i++) {
            int u  = tid + i * 256;        // float4 index 0..1023
            int k  = u >> 5;               // 0..31
            int n4 = u & 31;               // 0..31
            cp_async16(bB + k * (BSTR * 4) + n4 * 16,
                       W + (size_t)(kc * BK + k) * DOUT + n4 * 4);
        }
    };

    // ---- gather helper: one node, one list -> RN tf32 mean row in smem ----
    const float4* f4 = reinterpret_cast<const float4*>(fea1);
    const float sc = 1.0f / (float)KNEI;
    auto gather_node = [&](int node, int moff, const int* __restrict__ idx) {
        int n = (node < NNODES) ? node : (NNODES - 1);
        int myidx = idx[n * KNEI + lane];
        float4 a0 = make_float4(0.f, 0.f, 0.f, 0.f);
        float4 a1 = make_float4(0.f, 0.f, 0.f, 0.f);
        float4 a2 = make_float4(0.f, 0.f, 0.f, 0.f);
        float4 a3 = make_float4(0.f, 0.f, 0.f, 0.f);
        #pragma unroll
        for (int j = 0; j < KNEI; j += 4) {
            int i0 = __shfl_sync(0xffffffffu, myidx, j + 0);
            int i1 = __shfl_sync(0xffffffffu, myidx, j + 1);
            int i2 = __shfl_sync(0xffffffffu, myidx, j + 2);
            int i3 = __shfl_sync(0xffffffffu, myidx, j + 3);
            float4 v0 = __ldg(&f4[(size_t)i0 * (DIM / 4) + lane]);
            float4 v1 = __ldg(&f4[(size_t)i1 * (DIM / 4) + lane]);
            float4 v2 = __ldg(&f4[(size_t)i2 * (DIM / 4) + lane]);
            float4 v3 = __ldg(&f4[(size_t)i3 * (DIM / 4) + lane]);
            a0.x += v0.x; a0.y += v0.y; a0.z += v0.z; a0.w += v0.w;
            a1.x += v1.x; a1.y += v1.y; a1.z += v1.z; a1.w += v1.w;
            a2.x += v2.x; a2.y += v2.y; a2.z += v2.z; a2.w += v2.w;
            a3.x += v3.x; a3.y += v3.y; a3.z += v3.z; a3.w += v3.w;
        }
        float4 t;
        t.x = (a0.x + a1.x) + (a2.x + a3.x);
        t.y = (a0.y + a1.y) + (a2.y + a3.y);
        t.z = (a0.z + a1.z) + (a2.z + a3.z);
        t.w = (a0.w + a1.w) + (a2.w + a3.w);
        uint4 o;
        o.x = f2tf32(t.x * sc); o.y = f2tf32(t.y * sc);
        o.z = f2tf32(t.z * sc); o.w = f2tf32(t.w * sc);
        int r = node - block_row;          // always < 128
        *reinterpret_cast<uint4*>(&smem[moff + r * MSTR + lane * 4]) = o;
    };

    // ---- accumulators ----
    float acc[4][4][4];
    #pragma unroll
    for (int mt = 0; mt < 4; mt++)
        #pragma unroll
        for (int nt = 0; nt < 4; nt++)
            #pragma unroll
            for (int i = 0; i < 4; i++)
                acc[mt][nt][i] = 0.f;

    // ---- mma on one 32-wide K chunk ----
    auto do_mma = [&](const uint32_t* sA, int astride, bool cvtA,
                      const uint32_t* sB) {
        #pragma unroll
        for (int ks = 0; ks < 4; ks++) {
            const int ko = ks * 8;
            uint32_t af[4][4];
            #pragma unroll
            for (int mt = 0; mt < 4; mt++) {
                int row = warp_m + mt * 16 + gid;
                af[mt][0] = sA[row * astride + ko + tig];
                af[mt][1] = sA[(row + 8) * astride + ko + tig];
                af[mt][2] = sA[row * astride + ko + tig + 4];
                af[mt][3] = sA[(row + 8) * astride + ko + tig + 4];
                if (cvtA) {
                    #pragma unroll
                    for (int i = 0; i < 4; i++)
                        af[mt][i] = f2tf32(__uint_as_float(af[mt][i]));
                }
            }
            uint32_t bf[4][2];
            #pragma unroll
            for (int nt = 0; nt < 4; nt++) {
                int col = warp_n + nt * 8 + gid;
                bf[nt][0] = f2tf32(__uint_as_float(sB[(ko + tig) * BSTR + col]));
                bf[nt][1] = f2tf32(__uint_as_float(sB[(ko + tig + 4) * BSTR + col]));
            }
            #pragma unroll
            for (int mt = 0; mt < 4; mt++)
                #pragma unroll
                for (int nt = 0; nt < 4; nt++)
                    mma_tf32(acc[mt][nt], af[mt], bf[nt]);
        }
    };

    // ---- prologue ----
    load_A(0, 0);
    load_B(0, 0);
    CP_COMMIT();

    // ---- main loop: 16 K-chunks ----
    #pragma unroll 1
    for (int kc = 0; kc < 16; kc++) {
        CP_WAIT0();
        __syncthreads();
        if (kc + 1 < 16) {
            if (kc + 1 < 8) load_A(kc + 1, (kc + 1) & 1);
            load_B(kc + 1, (kc + 1) & 1);
        }
        CP_COMMIT();

        if (kc < 8) {
            // gather 2 nodes per warp this iteration (16 total over kc 0..7)
            int n0 = block_row + wid * 16 + kc * 2;
            gather_node(n0,     M1_OFF, idx1);
            gather_node(n0,     M2_OFF, idx2);
            gather_node(n0 + 1, M1_OFF, idx1);
            gather_node(n0 + 1, M2_OFF, idx2);
        }

        const uint32_t* sB = smem + (kc & 1) * STAGE_U32 + A_U32;
        if (kc < 8) {
            do_mma(smem + (kc & 1) * STAGE_U32, SSTR, true, sB);
        } else {
            const uint32_t* sA = smem + ((kc < 12) ? M1_OFF : M2_OFF) + (kc & 3) * BK;
            do_mma(sA, MSTR, false, sB);
        }
        __syncthreads();
    }

    // ---- epilogue: tanh + store ----
    #pragma unroll
    for (int mt = 0; mt < 4; mt++) {
        #pragma unroll
        for (int half = 0; half < 2; half++) {
            int gr = block_row + warp_m + mt * 16 + gid + half * 8;
            if (gr < NNODES) {
                #pragma unroll
                for (int nt = 0; nt < 4; nt++) {
                    float2 v;
                    v.x = tanhf(acc[mt][nt][half * 2 + 0]);
                    v.y = tanhf(acc[mt][nt][half * 2 + 1]);
                    *reinterpret_cast<float2*>(
                        out + (size_t)gr * DOUT + warp_n + nt * 8 + tig * 2) = v;
                }
            }
        }
    }
}

// ---------------------------------------------------------------------------
extern "C" void kernel_launch(void* const* d_in, const int* in_sizes, int n_in,
                              void* d_out, int out_size) {
    const float* node_fea1 = (const float*)d_in[0];
    const float* node_fea2 = (const float*)d_in[1];
    const int*   neigh1    = (const int*)  d_in[2];
    const int*   neigh2    = (const int*)  d_in[3];
    const float* weight    = (const float*)d_in[4];
    float*       out       = (float*)d_out;

    const int dyn_smem = SMEM_U32 * 4;   // 206848 B
    static bool attr_set = false;
    if (!attr_set) {
        cudaFuncSetAttribute(fused_kernel,
                             cudaFuncAttributeMaxDynamicSharedMemorySize, dyn_smem);
        attr_set = true;
    }
    fused_kernel<<<(NNODES + BM - 1) / BM, 256, dyn_smem>>>(
        node_fea1, node_fea2, neigh1, neigh2, weight, out);
}

// round 6
// speedup vs baseline: 1.4039x; 1.4039x over previous
#include <cuda_runtime.h>
#include <cuda_bf16.h>
#include <math.h>
#include <stdint.h>

#define NNODES 50000
#define KNEI   32
#define DIM    128
#define DOUT   128
#define KTOT   512
#define BM     128
#define BK     32
#define SSTR   36                   // A-stage row stride (u32)
#define BSTR   136                  // B-stage row stride (u32), [k][n] layout
#define A_U32  (BM * SSTR)          // 4608
#define B_U32  (BK * BSTR)          // 4352
#define STAGE_U32 (A_U32 + B_U32)   // 8960

// Static device scratch (allowed).
__device__ __nv_bfloat16 g_f1b[(size_t)NNODES * DIM];  // bf16(fea1), 12.8 MB
__device__ uint32_t g_n1t[(size_t)NNODES * DIM];       // tf32(mean nei1)
__device__ uint32_t g_n2t[(size_t)NNODES * DIM];       // tf32(mean nei2)
__device__ uint32_t g_Wt [(size_t)KTOT * DOUT];        // tf32(W), [k][n]

__device__ __forceinline__ uint32_t f2tf32(float f) {
    uint32_t u;
    asm("cvt.rna.tf32.f32 %0, %1;" : "=r"(u) : "f"(f));
    return u;
}
__device__ __forceinline__ uint32_t smem_u32p(const void* p) {
    uint32_t a;
    asm("{ .reg .u64 t; cvta.to.shared.u64 t, %1; cvt.u32.u64 %0, t; }" : "=r"(a) : "l"(p));
    return a;
}
__device__ __forceinline__ void cp_async16(uint32_t dst, const void* src) {
    asm volatile("cp.async.cg.shared.global [%0], [%1], 16;"
                 :: "r"(dst), "l"(src) : "memory");
}
#define CP_COMMIT() asm volatile("cp.async.commit_group;" ::: "memory")
#define CP_WAIT0()  asm volatile("cp.async.wait_group 0;"  ::: "memory")

__device__ __forceinline__ void mma_tf32(float c[4], const uint32_t a[4],
                                         const uint32_t b[2]) {
    asm volatile(
        "mma.sync.aligned.m16n8k8.row.col.f32.tf32.tf32.f32 "
        "{%0,%1,%2,%3}, {%4,%5,%6,%7}, {%8,%9}, {%0,%1,%2,%3};"
        : "+f"(c[0]), "+f"(c[1]), "+f"(c[2]), "+f"(c[3])
        : "r"(a[0]), "r"(a[1]), "r"(a[2]), "r"(a[3]), "r"(b[0]), "r"(b[1]));
}

// ---------------------------------------------------------------------------
// Kernel 1 (conv): fea1 -> bf16 (each thread 8 floats), W -> tf32 [k][n].
// grid = 3125 x 256 (800000 threads, exact for 6.4M floats).
// ---------------------------------------------------------------------------
__global__ __launch_bounds__(256)
void conv_kernel(const float* __restrict__ fea1, const float* __restrict__ W) {
    const int t = blockIdx.x * 256 + threadIdx.x;     // 0..799999
    {
        float4 a = reinterpret_cast<const float4*>(fea1)[2 * (size_t)t];
        float4 b = reinterpret_cast<const float4*>(fea1)[2 * (size_t)t + 1];
        __nv_bfloat162 p0 = __floats2bfloat162_rn(a.x, a.y);
        __nv_bfloat162 p1 = __floats2bfloat162_rn(a.z, a.w);
        __nv_bfloat162 p2 = __floats2bfloat162_rn(b.x, b.y);
        __nv_bfloat162 p3 = __floats2bfloat162_rn(b.z, b.w);
        uint4 o;
        o.x = *reinterpret_cast<uint32_t*>(&p0);
        o.y = *reinterpret_cast<uint32_t*>(&p1);
        o.z = *reinterpret_cast<uint32_t*>(&p2);
        o.w = *reinterpret_cast<uint32_t*>(&p3);
        reinterpret_cast<uint4*>(g_f1b)[t] = o;
    }
    if (t < (KTOT * DOUT) / 4) {                       // 16384 threads x 4
        float4 w = reinterpret_cast<const float4*>(W)[t];
        uint4 o;
        o.x = f2tf32(w.x); o.y = f2tf32(w.y); o.z = f2tf32(w.z); o.w = f2tf32(w.w);
        reinterpret_cast<uint4*>(g_Wt)[t] = o;
    }
}

// ---------------------------------------------------------------------------
// Kernel 2 (agg): one warp per node; gathers bf16 rows (256 B each),
// accumulates fp32, writes means as tf32 bits.
// ---------------------------------------------------------------------------
__global__ __launch_bounds__(256)
void agg_kernel(const int* __restrict__ idx1, const int* __restrict__ idx2) {
    const int node = blockIdx.x * 8 + (threadIdx.x >> 5);   // exact 50000
    const int lane = threadIdx.x & 31;
    const uint2* fb = reinterpret_cast<const uint2*>(g_f1b);
    const float sc = 1.0f / (float)KNEI;

    #pragma unroll
    for (int list = 0; list < 2; list++) {
        const int* idx = list ? idx2 : idx1;
        uint32_t*  dst = list ? g_n2t : g_n1t;
        int myidx = idx[node * KNEI + lane];
        float4 a0 = make_float4(0.f, 0.f, 0.f, 0.f);
        float4 a1 = make_float4(0.f, 0.f, 0.f, 0.f);
        #pragma unroll
        for (int j = 0; j < KNEI; j += 2) {
            int i0 = __shfl_sync(0xffffffffu, myidx, j + 0);
            int i1 = __shfl_sync(0xffffffffu, myidx, j + 1);
            uint2 v0 = __ldg(&fb[(size_t)i0 * 32 + lane]);
            uint2 v1 = __ldg(&fb[(size_t)i1 * 32 + lane]);
            float2 l0 = __bfloat1622float2(*reinterpret_cast<__nv_bfloat162*>(&v0.x));
            float2 h0 = __bfloat1622float2(*reinterpret_cast<__nv_bfloat162*>(&v0.y));
            float2 l1 = __bfloat1622float2(*reinterpret_cast<__nv_bfloat162*>(&v1.x));
            float2 h1 = __bfloat1622float2(*reinterpret_cast<__nv_bfloat162*>(&v1.y));
            a0.x += l0.x; a0.y += l0.y; a0.z += h0.x; a0.w += h0.y;
            a1.x += l1.x; a1.y += l1.y; a1.z += h1.x; a1.w += h1.y;
        }
        uint4 o;
        o.x = f2tf32((a0.x + a1.x) * sc);
        o.y = f2tf32((a0.y + a1.y) * sc);
        o.z = f2tf32((a0.z + a1.z) * sc);
        o.w = f2tf32((a0.w + a1.w) * sc);
        *reinterpret_cast<uint4*>(&dst[(size_t)node * DIM + lane * 4]) = o;
    }
}

// ---------------------------------------------------------------------------
// Kernel 3: tf32 mma GEMM + tanh, 2-stage cp.async ping-pong.
// A: kc 0..7 raw fp32 fea1/fea2 (reg cvt); kc 8..15 tf32 means (no cvt).
// B: tf32 W, [k][n] smem layout (stride 136).
// ---------------------------------------------------------------------------
__global__ __launch_bounds__(256, 2)
void gemm_mma_kernel(const float* __restrict__ fea1,
                     const float* __restrict__ fea2,
                     float* __restrict__ out) {
    extern __shared__ uint32_t smem[];

    const int tid  = threadIdx.x;
    const int wid  = tid >> 5;
    const int lane = tid & 31;
    const int gid  = lane >> 2;
    const int tig  = lane & 3;
    const int warp_m = (wid >> 2) * 64;
    const int warp_n = (wid & 3) * 32;
    const int block_row = blockIdx.x * BM;
    const uint32_t sbase = smem_u32p(smem);

    auto load_chunk = [&](int kc, int stage) {
        const uint32_t aB = sbase + stage * (STAGE_U32 * 4);
        const uint32_t bB = aB + A_U32 * 4;
        const void* Abase;
        if (kc < 4)       Abase = fea1;
        else if (kc < 8)  Abase = fea2;
        else if (kc < 12) Abase = g_n1t;
        else              Abase = g_n2t;
        const uint32_t* A = reinterpret_cast<const uint32_t*>(Abase);
        const int colb = (kc & 3) * BK;
        #pragma unroll
        for (int i = 0; i < 4; i++) {
            int u  = tid + i * 256;
            int r  = u >> 3;               // 0..127
            int c4 = u & 7;                // 0..7
            int gr = block_row + r;
            if (gr >= NNODES) gr = NNODES - 1;
            cp_async16(aB + r * (SSTR * 4) + c4 * 16,
                       A + (size_t)gr * DIM + colb + c4 * 4);
        }
        #pragma unroll
        for (int i = 0; i < 4; i++) {
            int u  = tid + i * 256;        // float4 idx 0..1023
            int k  = u >> 5;               // 0..31
            int n4 = u & 31;               // 0..31
            cp_async16(bB + k * (BSTR * 4) + n4 * 16,
                       g_Wt + (size_t)(kc * BK + k) * DOUT + n4 * 4);
        }
    };

    float acc[4][4][4];
    #pragma unroll
    for (int mt = 0; mt < 4; mt++)
        #pragma unroll
        for (int nt = 0; nt < 4; nt++)
            #pragma unroll
            for (int i = 0; i < 4; i++)
                acc[mt][nt][i] = 0.f;

    load_chunk(0, 0);
    CP_COMMIT();

    #pragma unroll 1
    for (int kc = 0; kc < 16; kc++) {
        CP_WAIT0();
        __syncthreads();
        if (kc + 1 < 16) load_chunk(kc + 1, (kc + 1) & 1);
        CP_COMMIT();

        const uint32_t* sA = smem + (kc & 1) * STAGE_U32;
        const uint32_t* sB = sA + A_U32;
        const bool cvtA = (kc < 8);

        #pragma unroll
        for (int ks = 0; ks < 4; ks++) {
            const int ko = ks * 8;
            uint32_t af[4][4];
            #pragma unroll
            for (int mt = 0; mt < 4; mt++) {
                int row = warp_m + mt * 16 + gid;
                af[mt][0] = sA[row * SSTR + ko + tig];
                af[mt][1] = sA[(row + 8) * SSTR + ko + tig];
                af[mt][2] = sA[row * SSTR + ko + tig + 4];
                af[mt][3] = sA[(row + 8) * SSTR + ko + tig + 4];
                if (cvtA) {
                    #pragma unroll
                    for (int i = 0; i < 4; i++)
                        af[mt][i] = f2tf32(__uint_as_float(af[mt][i]));
                }
            }
            uint32_t bf[4][2];
            #pragma unroll
            for (int nt = 0; nt < 4; nt++) {
                int col = warp_n + nt * 8 + gid;
                bf[nt][0] = sB[(ko + tig) * BSTR + col];
                bf[nt][1] = sB[(ko + tig + 4) * BSTR + col];
            }
            #pragma unroll
            for (int mt = 0; mt < 4; mt++)
                #pragma unroll
                for (int nt = 0; nt < 4; nt++)
                    mma_tf32(acc[mt][nt], af[mt], bf[nt]);
        }
        __syncthreads();
    }

    #pragma unroll
    for (int mt = 0; mt < 4; mt++) {
        #pragma unroll
        for (int half = 0; half < 2; half++) {
            int gr = block_row + warp_m + mt * 16 + gid + half * 8;
            if (gr < NNODES) {
                #pragma unroll
                for (int nt = 0; nt < 4; nt++) {
                    float2 v;
                    v.x = tanhf(acc[mt][nt][half * 2 + 0]);
                    v.y = tanhf(acc[mt][nt][half * 2 + 1]);
                    *reinterpret_cast<float2*>(
                        out + (size_t)gr * DOUT + warp_n + nt * 8 + tig * 2) = v;
                }
            }
        }
    }
}

// ---------------------------------------------------------------------------
extern "C" void kernel_launch(void* const* d_in, const int* in_sizes, int n_in,
                              void* d_out, int out_size) {
    const float* node_fea1 = (const float*)d_in[0];
    const float* node_fea2 = (const float*)d_in[1];
    const int*   neigh1    = (const int*)  d_in[2];
    const int*   neigh2    = (const int*)  d_in[3];
    const float* weight    = (const float*)d_in[4];
    float*       out       = (float*)d_out;

    conv_kernel<<<(NNODES * DIM / 8 + 255) / 256, 256>>>(node_fea1, weight);
    agg_kernel<<<NNODES / 8, 256>>>(neigh1, neigh2);

    const int dyn_smem = 2 * STAGE_U32 * 4;   // 71680 B
    static bool attr_set = false;
    if (!attr_set) {
        cudaFuncSetAttribute(gemm_mma_kernel,
                             cudaFuncAttributeMaxDynamicSharedMemorySize, dyn_smem);
        attr_set = true;
    }
    gemm_mma_kernel<<<(NNODES + BM - 1) / BM, 256, dyn_smem>>>(
        node_fea1, node_fea2, out);
}